// round 7
// baseline (speedup 1.0000x reference)
#include <cuda_runtime.h>
#include <cstdint>

// x: [64, 3, 512, 512] float32
// keep_mask: [64, 32, 32] -> widened to 32-bit words (nonzero == keep)
// out = x * upsample16(keep_mask)
//
// R7: keep R4/R6 elision (32B/thread/slot, predicated reads) but software-
// pipeline: each thread owns ITER=4 grid-stride-distant groups; all 4 mask
// loads issue up front (independent), then 4 predicated load/store slots.
// Removes mask->data serialization from the critical path, raising read MLP.

static constexpr int B = 64;
static constexpr int C = 3;
static constexpr int H = 512;
static constexpr int W = 512;
static constexpr long long N  = (long long)B * C * H * W;  // 50,331,648 floats
static constexpr long long N8 = N / 8;                     // 6,291,456 groups
static constexpr int ITER = 4;
static constexpr long long STRIDE = N8 / ITER;             // 1,572,864 (exact)

__global__ void __launch_bounds__(256) patchmask_kernel(
    const float4* __restrict__ x4,
    const uint32_t* __restrict__ keep,
    float4* __restrict__ out4)
{
    long long t = (long long)blockIdx.x * blockDim.x + threadIdx.x;
    if (t >= STRIDE) return;

    // Phase 1: issue all mask loads (independent of each other)
    bool m[ITER];
#pragma unroll
    for (int k = 0; k < ITER; k++) {
        long long i = t + (long long)k * STRIDE;
        long long base = i << 3;               // float index
        int w  = (int)(base & (W - 1));
        int h  = (int)((base >> 9) & (H - 1));
        int b  = (int)(base >> 18) / C;
        m[k] = __ldg(keep + b * 1024 + ((h >> 4) << 5) + (w >> 4)) != 0u;
    }

    // Phase 2: predicated data loads + stores per slot (slots independent)
    const float4 z = make_float4(0.f, 0.f, 0.f, 0.f);
#pragma unroll
    for (int k = 0; k < ITER; k++) {
        long long j = (t + (long long)k * STRIDE) << 1;   // float4 index
        float4 v0 = m[k] ? __ldcs(x4 + j)     : z;
        float4 v1 = m[k] ? __ldcs(x4 + j + 1) : z;
        __stcs(out4 + j,     v0);
        __stcs(out4 + j + 1, v1);
    }
}

extern "C" void kernel_launch(void* const* d_in, const int* in_sizes, int n_in,
                              void* d_out, int out_size)
{
    const float4*   x4   = (const float4*)d_in[0];
    const uint32_t* keep = (const uint32_t*)d_in[1];
    float4*         out4 = (float4*)d_out;

    const int threads = 256;
    const long long blocks = (STRIDE + threads - 1) / threads;  // 6144
    patchmask_kernel<<<(unsigned)blocks, threads>>>(x4, keep, out4);
}